// round 11
// baseline (speedup 1.0000x reference)
#include <cuda_runtime.h>
#include <cstddef>

namespace {

constexpr int B = 8, T = 2048, H = 256, L = 16;
constexpr int S = 16;                  // t-strip per main block
constexpr int THREADS = 128;           // 4 warps: (g_l in {0,1}) x (g_h in {0,1})
constexpr int STRIPS_PER_B = T / S;    // 128
constexpr int MAIN_BLOCKS  = B * STRIPS_PER_B;    // 1024
constexpr int RELAY_BLOCKS = 128;                  // 512 warps x 32 t
constexpr int GRID = MAIN_BLOCKS + RELAY_BLOCKS;   // 1152
constexpr int RELAY_T_PER_WARP = (B * T) / (RELAY_BLOCKS * 4);  // 32

struct R4f { float v[4]; };
struct R8  { float v[8]; };
struct TrueT  { static constexpr bool value = true;  };
struct FalseT { static constexpr bool value = false; };

// Half-row load: 4 consecutive floats of row `row` at float-offset `off`.
// CHK=true: zeros when row OOB (reference's zero padding).
template <bool CHK>
__device__ __forceinline__ R4f load_row4(const float* __restrict__ base, int row, int off) {
  R4f r;
  if (!CHK || (unsigned)row < (unsigned)T) {
    float4 a = *reinterpret_cast<const float4*>(base + (size_t)row * H + off);
    r.v[0] = a.x; r.v[1] = a.y; r.v[2] = a.z; r.v[3] = a.w;
  } else {
    r.v[0] = r.v[1] = r.v[2] = r.v[3] = 0.f;
  }
  return r;
}

// Full-row (8-float) load for the relay path.
template <bool CHK>
__device__ __forceinline__ R8 load_row8(const float* __restrict__ base, int row, int hbase) {
  R8 r;
  if (!CHK || (unsigned)row < (unsigned)T) {
    const float4* p = reinterpret_cast<const float4*>(base + (size_t)row * H + hbase);
    float4 a = p[0];
    float4 b = p[1];
    r.v[0] = a.x; r.v[1] = a.y; r.v[2] = a.z; r.v[3] = a.w;
    r.v[4] = b.x; r.v[5] = b.y; r.v[6] = b.z; r.v[7] = b.w;
  } else {
#pragma unroll
    for (int j = 0; j < 8; j++) r.v[j] = 0.f;
  }
  return r;
}

// Interleaved merge: lanes with (lane&s)==0 carry the a-class partial sum,
// lanes with (lane&s)!=0 the b-class. One shfl per merge.
__device__ __forceinline__ float shfl_merge(float a, float b, int s, int lane) {
  const bool hi = (lane & s) != 0;
  float send = hi ? a : b;
  float recv = __shfl_xor_sync(0xffffffffu, send, s);
  return (hi ? b : a) + recv;
}

__global__ __launch_bounds__(THREADS, 4)
void ffm_kernel(const float* __restrict__ logits,
                const float* __restrict__ end_w,
                const float* __restrict__ whole_w,
                const float* __restrict__ relay_w,
                const float* __restrict__ relay_b,
                const float* __restrict__ length_bias,
                float* __restrict__ out,
                float* __restrict__ relay_out) {
  const int warp = threadIdx.x >> 5;
  const int lane = threadIdx.x & 31;

  if (blockIdx.x >= MAIN_BLOCKS) {
    // ---------------- relay blocks ----------------
    // relay[b,t] = sum_h max(x[b,t,h], x_pad[b,t+L,h]) * relay_w[h] + relay_b
    const int wglob = (blockIdx.x - MAIN_BLOCKS) * 4 + warp;   // [0, 512)
    const int base_t = wglob * RELAY_T_PER_WARP;
    const int b  = base_t / T;
    const int t0 = base_t % T;
    const int hbase = lane * 8;
    const float* lb = logits + (size_t)b * T * H;

    float rw[8];
#pragma unroll
    for (int q = 0; q < 2; q++) {
      float4 xr = *reinterpret_cast<const float4*>(relay_w + hbase + 4 * q);
      rw[4*q+0]=xr.x; rw[4*q+1]=xr.y; rw[4*q+2]=xr.z; rw[4*q+3]=xr.w;
    }
    const float rb = relay_b[0];

    for (int k = 0; k < RELAY_T_PER_WARP; k += 2) {
      const int t = t0 + k;
      R8 cur0 = load_row8<false>(lb, t, hbase);
      R8 cur1 = load_row8<false>(lb, t + 1, hbase);
      R8 nxt0 = load_row8<true>(lb, t + L, hbase);
      R8 nxt1 = load_row8<true>(lb, t + L + 1, hbase);

      float rel0 = 0.f, rel1 = 0.f;
#pragma unroll
      for (int j = 0; j < 8; j++) {
        rel0 = fmaf(fmaxf(cur0.v[j], nxt0.v[j]), rw[j], rel0);
        rel1 = fmaf(fmaxf(cur1.v[j], nxt1.v[j]), rw[j], rel1);
      }
      float m = shfl_merge(rel0, rel1, 16, lane);  // bit16: 0→t, 1→t+1
      m += __shfl_xor_sync(0xffffffffu, m, 8);
      m += __shfl_xor_sync(0xffffffffu, m, 4);
      m += __shfl_xor_sync(0xffffffffu, m, 2);
      m += __shfl_xor_sync(0xffffffffu, m, 1);
      if ((lane & 15) == 0)
        relay_out[(size_t)b * T + t + (lane >> 4)] = m + rb;
    }
    return;
  }

  // ---------------- main blocks ----------------
  // Warp (g_l, g_h): g_l picks l in [8*g_l, 8*g_l+8), g_h picks h-half.
  const int g_l = warp & 1;
  const int g_h = warp >> 1;
  const int off = g_h * 128 + lane * 4;   // this lane's 4-float H slice

  const int strip = blockIdx.x;
  const int b     = strip / STRIPS_PER_B;
  const int s0    = (strip % STRIPS_PER_B) * S;

  __shared__ float part[2][S][L];         // [g_h][t][l] partial sums

  // Weights in registers (half-width): 8 l's x 4 floats, plus end_w slice.
  float w[8][4], ew[4];
#pragma unroll
  for (int k = 0; k < 8; k++) {
    float4 x = *reinterpret_cast<const float4*>(whole_w + (8 * g_l + k) * H + off);
    w[k][0] = x.x; w[k][1] = x.y; w[k][2] = x.z; w[k][3] = x.w;
  }
  {
    float4 x = *reinterpret_cast<const float4*>(end_w + off);
    ew[0] = x.x; ew[1] = x.y; ew[2] = x.z; ew[3] = x.w;
  }
  // Tree classes: k = bit16 + 2*bit8 + 4*bit4. Writers: lane&3 == 0.
  const int  k_idx  = ((lane >> 4) & 1) + 2 * ((lane >> 3) & 1) + 4 * ((lane >> 2) & 1);
  const bool writer = (lane & 3) == 0;

  const float* lb = logits + (size_t)b * T * H;

  auto body = [&](auto chk_tag) {
    constexpr bool CHK = decltype(chk_tag)::value;

    // 8-row circular window (half-rows). At step u (p = u & 7): slot p gets
    // row r - 8*g_l; slot (p-k)&7 holds row r - 8*g_l - k.
    R4f Wn[8];
#pragma unroll
    for (int k = 1; k <= 7; k++)
      Wn[(8 - k) & 7] = load_row4<CHK>(lb, s0 - 8 * g_l - k, off);

    for (int u0 = 0; u0 < S; u0 += 8) {
#pragma unroll
      for (int p = 0; p < 8; p++) {
        const int r = s0 + u0 + p;

        Wn[p] = load_row4<CHK>(lb, r - 8 * g_l, off);   // advance window
        R4f cur;
        if (g_l == 0) cur = Wn[p];                      // l-group 0: slot p IS row r
        else          cur = load_row4<false>(lb, r, off);

        float e = 0.f;
        float acc[8];
#pragma unroll
        for (int k = 0; k < 8; k++) acc[k] = 0.f;
#pragma unroll
        for (int j = 0; j < 4; j++) {
          const float c = cur.v[j];
          e = fmaf(c, ew[j], e);
#pragma unroll
          for (int k = 0; k < 8; k++)
            acc[k] = fmaf(fmaxf(c, Wn[(p + 8 - k) & 7].v[j]), w[k][j], acc[k]);
        }
#pragma unroll
        for (int k = 0; k < 8; k++) acc[k] += e;  // fold end partial

        // Fused 8-value interleaved tree: 9 shfls.
        float m0 = shfl_merge(acc[0], acc[1], 16, lane);
        float m1 = shfl_merge(acc[2], acc[3], 16, lane);
        float m2 = shfl_merge(acc[4], acc[5], 16, lane);
        float m3 = shfl_merge(acc[6], acc[7], 16, lane);
        float n0 = shfl_merge(m0, m1, 8, lane);
        float n1 = shfl_merge(m2, m3, 8, lane);
        float z  = shfl_merge(n0, n1, 4, lane);
        z += __shfl_xor_sync(0xffffffffu, z, 2);
        z += __shfl_xor_sync(0xffffffffu, z, 1);

        if (writer)
          part[g_h][u0 + p][8 * g_l + k_idx] = z;
      }
    }
  };

  // Min row touched: s0 - 15 (g_l=1 prefill). Interior strips skip checks.
  if (s0 >= 16) body(FalseT{});
  else          body(TrueT{});

  __syncthreads();

  // Combine h-halves + bias; 2 outputs per thread, fully coalesced.
  {
    const int idx = 2 * threadIdx.x;          // flat (t, l), l even
    const int t = idx >> 4;
    const int l = idx & 15;
    float2 o;
    o.x = part[0][t][l]     + part[1][t][l]     + length_bias[l];
    o.y = part[0][t][l + 1] + part[1][t][l + 1] + length_bias[l + 1];
    *reinterpret_cast<float2*>(out + (size_t)(b * T + s0 + t) * L + l) = o;
  }
}

}  // namespace

extern "C" void kernel_launch(void* const* d_in, const int* in_sizes, int n_in,
                              void* d_out, int out_size) {
  const float* logits  = (const float*)d_in[0];
  const float* end_w   = (const float*)d_in[1];
  const float* whole_w = (const float*)d_in[2];
  const float* relay_w = (const float*)d_in[3];
  const float* relay_b = (const float*)d_in[4];
  const float* lbias   = (const float*)d_in[5];

  float* out   = (float*)d_out;                // [B, T, L]
  float* relay = out + (size_t)B * T * L;      // [B, T] appended

  ffm_kernel<<<GRID, THREADS>>>(logits, end_w, whole_w, relay_w, relay_b,
                                lbias, out, relay);
}

// round 13
// speedup vs baseline: 1.0091x; 1.0091x over previous
#include <cuda_runtime.h>
#include <cstddef>

namespace {

constexpr int B = 8, T = 2048, H = 256, L = 16;
constexpr int S = 16;                  // t-strip per main block
constexpr int WARPS = 4;               // warp g owns l in [4g, 4g+3]
constexpr int THREADS = WARPS * 32;    // 128
constexpr int STRIPS_PER_B = T / S;    // 128
constexpr int MAIN_BLOCKS  = B * STRIPS_PER_B;    // 1024
constexpr int RELAY_BLOCKS = 128;                  // 512 warps x 32 t
constexpr int GRID = MAIN_BLOCKS + RELAY_BLOCKS;   // 1152
constexpr int RELAY_T_PER_WARP = (B * T) / (RELAY_BLOCKS * WARPS);  // 32

using u64 = unsigned long long;
struct P4 { u64 v[4]; };               // 8 floats as 4 packed f32x2
struct TrueT  { static constexpr bool value = true;  };
struct FalseT { static constexpr bool value = false; };

// ---- packed f32x2 helpers ----
// fma.rn.f32x2 is real PTX on sm_100+ (emits FFMA2).
__device__ __forceinline__ u64 fma2(u64 a, u64 b, u64 c) {
  u64 r;
  asm("fma.rn.f32x2 %0, %1, %2, %3;" : "=l"(r) : "l"(a), "l"(b), "l"(c));
  return r;
}
// Packed max emulated on halves. mov.b64 pack/unpack are register-pair
// renames (zero SASS instructions), so this costs exactly 2 FMNMX.
__device__ __forceinline__ u64 max2(u64 a, u64 b) {
  float alo, ahi, blo, bhi;
  asm("mov.b64 {%0, %1}, %2;" : "=f"(alo), "=f"(ahi) : "l"(a));
  asm("mov.b64 {%0, %1}, %2;" : "=f"(blo), "=f"(bhi) : "l"(b));
  float rlo = fmaxf(alo, blo);
  float rhi = fmaxf(ahi, bhi);
  u64 r;
  asm("mov.b64 %0, {%1, %2};" : "=l"(r) : "f"(rlo), "f"(rhi));
  return r;
}
__device__ __forceinline__ float collapse(u64 p) {  // lo + hi
  float lo, hi;
  asm("mov.b64 {%0, %1}, %2;" : "=f"(lo), "=f"(hi) : "l"(p));
  return lo + hi;
}

// Load 8 floats of row `row` (lane's H-slice) as 4 packed f32x2.
// CHK=true: zeros when row OOB (reference's zero padding).
template <bool CHK>
__device__ __forceinline__ P4 load_rowp(const float* __restrict__ base, int row, int hbase) {
  P4 r;
  if (!CHK || (unsigned)row < (unsigned)T) {
    const ulonglong2* p = reinterpret_cast<const ulonglong2*>(base + (size_t)row * H + hbase);
    ulonglong2 a = p[0];
    ulonglong2 b = p[1];
    r.v[0] = a.x; r.v[1] = a.y; r.v[2] = b.x; r.v[3] = b.y;
  } else {
    r.v[0] = r.v[1] = r.v[2] = r.v[3] = 0ull;   // == {0.f, 0.f}
  }
  return r;
}

// Interleaved merge: lanes with (lane&s)==0 carry the a-class partial sum,
// lanes with (lane&s)!=0 the b-class. One shfl per merge.
__device__ __forceinline__ float shfl_merge(float a, float b, int s, int lane) {
  const bool hi = (lane & s) != 0;
  float send = hi ? a : b;
  float recv = __shfl_xor_sync(0xffffffffu, send, s);
  return (hi ? b : a) + recv;
}

__global__ __launch_bounds__(THREADS, 4)
void ffm_kernel(const float* __restrict__ logits,
                const float* __restrict__ end_w,
                const float* __restrict__ whole_w,
                const float* __restrict__ relay_w,
                const float* __restrict__ relay_b,
                const float* __restrict__ length_bias,
                float* __restrict__ out,
                float* __restrict__ relay_out) {
  const int g    = threadIdx.x >> 5;
  const int lane = threadIdx.x & 31;
  const int hbase = lane * 8;

  if (blockIdx.x >= MAIN_BLOCKS) {
    // ---------------- relay blocks ----------------
    // relay[b,t] = sum_h max(x[b,t,h], x_pad[b,t+L,h]) * relay_w[h] + relay_b
    const int wglob = (blockIdx.x - MAIN_BLOCKS) * WARPS + g;   // [0, 512)
    const int base_t = wglob * RELAY_T_PER_WARP;
    const int b  = base_t / T;
    const int t0 = base_t % T;
    const float* lb = logits + (size_t)b * T * H;

    P4 rw = load_rowp<false>(relay_w, 0, hbase);
    const float rb = relay_b[0];

    for (int k = 0; k < RELAY_T_PER_WARP; k += 2) {
      const int t = t0 + k;
      P4 cur0 = load_rowp<false>(lb, t, hbase);
      P4 cur1 = load_rowp<false>(lb, t + 1, hbase);
      P4 nxt0 = load_rowp<true>(lb, t + L, hbase);
      P4 nxt1 = load_rowp<true>(lb, t + L + 1, hbase);

      u64 R0 = 0ull, R1 = 0ull;
#pragma unroll
      for (int j = 0; j < 4; j++) {
        R0 = fma2(max2(cur0.v[j], nxt0.v[j]), rw.v[j], R0);
        R1 = fma2(max2(cur1.v[j], nxt1.v[j]), rw.v[j], R1);
      }
      float rel0 = collapse(R0), rel1 = collapse(R1);

      float m = shfl_merge(rel0, rel1, 16, lane);  // bit16: 0→t, 1→t+1
      m += __shfl_xor_sync(0xffffffffu, m, 8);
      m += __shfl_xor_sync(0xffffffffu, m, 4);
      m += __shfl_xor_sync(0xffffffffu, m, 2);
      m += __shfl_xor_sync(0xffffffffu, m, 1);
      if ((lane & 15) == 0)
        relay_out[(size_t)b * T + t + (lane >> 4)] = m + rb;
    }
    return;
  }

  // ---------------- main blocks ----------------
  const int strip = blockIdx.x;
  const int b     = strip / STRIPS_PER_B;
  const int s0    = (strip % STRIPS_PER_B) * S;

  // Weights in registers (packed) for the whole strip.
  P4 w0, w1, w2, w3, ew;
  w0 = load_rowp<false>(whole_w + (4 * g + 0) * H, 0, hbase);
  w1 = load_rowp<false>(whole_w + (4 * g + 1) * H, 0, hbase);
  w2 = load_rowp<false>(whole_w + (4 * g + 2) * H, 0, hbase);
  w3 = load_rowp<false>(whole_w + (4 * g + 3) * H, 0, hbase);
  ew = load_rowp<false>(end_w, 0, hbase);

  // Writer lanes 0,16,8,24 hold finished sums for l = 4g + idx,
  // idx = bit16 + 2*bit8.
  const int  idx    = ((lane >> 4) & 1) + ((lane >> 3) & 1) * 2;
  const bool writer = (lane & 7) == 0;
  const float bias  = length_bias[4 * g + idx];

  const float* lb = logits + (size_t)b * T * H;

  auto body = [&](auto chk_tag) {
    constexpr bool CHK = decltype(chk_tag)::value;

    // 4-row circular window. Row (s0 + u - 4g) loaded at step u into slot u&3;
    // at step u (p = u & 3), row r-4g-k lives in slot (p - k) & 3.
    P4 Wn[4];
#pragma unroll
    for (int k = 1; k <= 3; k++)
      Wn[(4 - k) & 3] = load_rowp<CHK>(lb, s0 - 4 * g - k, hbase);

#pragma unroll
    for (int u = 0; u < S; u++) {
      const int p = u & 3;
      const int r = s0 + u;

      Wn[p] = load_rowp<CHK>(lb, r - 4 * g, hbase);  // advance window
      P4 cur;
      if (g == 0) cur = Wn[p];                       // warp 0: window row IS row r
      else        cur = load_rowp<false>(lb, r, hbase);

      u64 E = 0ull, A0 = 0ull, A1 = 0ull, A2 = 0ull, A3 = 0ull;
#pragma unroll
      for (int j = 0; j < 4; j++) {
        const u64 c = cur.v[j];
        E  = fma2(c, ew.v[j], E);
        A0 = fma2(max2(c, Wn[p].v[j]),           w0.v[j], A0);  // l = 4g
        A1 = fma2(max2(c, Wn[(p + 3) & 3].v[j]), w1.v[j], A1);  // l = 4g+1
        A2 = fma2(max2(c, Wn[(p + 2) & 3].v[j]), w2.v[j], A2);  // l = 4g+2
        A3 = fma2(max2(c, Wn[(p + 1) & 3].v[j]), w3.v[j], A3);  // l = 4g+3
      }
      // Collapse hi/lo halves and fold the end-score partial.
      const float e = collapse(E);
      float a0 = collapse(A0) + e;
      float a1 = collapse(A1) + e;
      float a2 = collapse(A2) + e;
      float a3 = collapse(A3) + e;

      // Interleaved 4-value warp reduction: 5 shfl total.
      float x = shfl_merge(a0, a1, 16, lane);
      float y = shfl_merge(a2, a3, 16, lane);
      float z = shfl_merge(x,  y,  8,  lane);
      z += __shfl_xor_sync(0xffffffffu, z, 4);
      z += __shfl_xor_sync(0xffffffffu, z, 2);
      z += __shfl_xor_sync(0xffffffffu, z, 1);

      if (writer)
        out[(size_t)(b * T + r) * L + 4 * g + idx] = z + bias;
    }
  };

  // Min row touched is s0-15 (warp 3 prefill); max row s0+S-1 < T.
  if (s0 >= 16) body(FalseT{});
  else          body(TrueT{});
}

}  // namespace

extern "C" void kernel_launch(void* const* d_in, const int* in_sizes, int n_in,
                              void* d_out, int out_size) {
  const float* logits  = (const float*)d_in[0];
  const float* end_w   = (const float*)d_in[1];
  const float* whole_w = (const float*)d_in[2];
  const float* relay_w = (const float*)d_in[3];
  const float* relay_b = (const float*)d_in[4];
  const float* lbias   = (const float*)d_in[5];

  float* out   = (float*)d_out;                // [B, T, L]
  float* relay = out + (size_t)B * T * L;      // [B, T] appended

  ffm_kernel<<<GRID, THREADS>>>(logits, end_w, whole_w, relay_w, relay_b,
                                lbias, out, relay);
}